// round 17
// baseline (speedup 1.0000x reference)
#include <cuda_runtime.h>
#include <cuda_fp16.h>
#include <math.h>
#include <stdint.h>

// ----------------------------- problem constants ---------------------------
#define CC   768
#define TT   1024
#define BBATCH 4
#define MM   (BBATCH*TT)
#define NHD  24
#define HSZ  32
#define HP_  32
#define WP_  32
#define C4   (CC/4)
#define CL   32
#define NCH  32

#define SSLOT 3145728ull
__device__ float g_scratch[16ull*SSLOT];

enum { EP_NONE = 0, EP_TANH = 1, EP_SILU = 2, EP_EXPW = 3, EP_MIX = 4 };

// ------------------------- fast transcendental helpers ----------------------
__device__ __forceinline__ float fast_tanh(float x) {
    x = fminf(fmaxf(x, -15.f), 15.f);
    float e = __expf(2.f * x);
    return __fdividef(e - 1.f, e + 1.f);
}
__device__ __forceinline__ float fast_silu(float x) {
    return __fdividef(x, 1.f + __expf(-x));
}

// ----------------------------- MMA helpers ---------------------------------
__device__ __forceinline__ void mma_f16(float acc[4], const uint32_t a[4],
                                        const uint32_t b0, const uint32_t b1) {
    asm volatile(
        "mma.sync.aligned.m16n8k16.row.col.f32.f16.f16.f32 "
        "{%0,%1,%2,%3}, {%4,%5,%6,%7}, {%8,%9}, {%0,%1,%2,%3};"
        : "+f"(acc[0]), "+f"(acc[1]), "+f"(acc[2]), "+f"(acc[3])
        : "r"(a[0]), "r"(a[1]), "r"(a[2]), "r"(a[3]), "r"(b0), "r"(b1));
}

#define LDSM4(d0, d1, d2, d3, addr)                                           \
    asm volatile("ldmatrix.sync.aligned.m8n8.x4.shared.b16 {%0,%1,%2,%3}, [%4];" \
                 : "=r"(d0), "=r"(d1), "=r"(d2), "=r"(d3) : "r"(addr));

__device__ __forceinline__ void cpasync16(uint32_t saddr, const void* gptr) {
    asm volatile("cp.async.cg.shared.global [%0], [%1], 16;"
                 :: "r"(saddr), "l"(gptr));
}

// --------------------- weight transpose + fp16 convert ----------------------
#define NTR 8
struct TArgs {
    const float* src[NTR];
    __half*      dst[NTR];
    int K[NTR];
    int N[NTR];
    int Np[NTR];
};

__global__ void transpose_kernel(TArgs ta)
{
    __shared__ float tile[32][33];
    const int z = blockIdx.z;
    const int K = ta.K[z], N = ta.N[z], Np = ta.Np[z];
    const int x0 = blockIdx.x * 32;
    const int y0 = blockIdx.y * 32;
    if (x0 >= Np || y0 >= K) return;
    const float* src = ta.src[z];
    __half* dst = ta.dst[z];
    const int tx = threadIdx.x, ty = threadIdx.y;
#pragma unroll
    for (int j = 0; j < 4; j++) {
        int k = y0 + ty + 8 * j;
        int n = x0 + tx;
        tile[ty + 8 * j][tx] = (n < N) ? src[(size_t)k * N + n] : 0.f;
    }
    __syncthreads();
#pragma unroll
    for (int j = 0; j < 4; j++) {
        int n = x0 + ty + 8 * j;
        int k = y0 + tx;
        dst[(size_t)n * K + k] = __float2half_rn(tile[tx][ty + 8 * j]);
    }
}

// ---------------- build block-diagonal mix weight Bmix[3840][160] -----------
__global__ void build_bmix_kernel(const float* __restrict__ w2,
                                  __half* __restrict__ bmix)
{
    int idx = blockIdx.x * blockDim.x + threadIdx.x;
    if (idx >= 3840 * 160) return;
    int row = idx / 160;
    int kcol = idx % 160;
    int q = row / 768;
    int c = row % 768;
    float v = 0.f;
    if (kcol / 32 == q)
        v = w2[(size_t)q * 32 * 768 + (size_t)(kcol % 32) * 768 + c];
    bmix[idx] = __float2half_rn(v);
}

// ---------------- split-K reduce for G1: tanh(sum of 4 parts) -> half -------
__global__ void g1_reduce_kernel(const float* __restrict__ part,
                                 __half* __restrict__ g1)
{
    int idx = blockIdx.x * blockDim.x + threadIdx.x;
    if (idx >= MM * 160 / 4) return;
    float4 p0 = ((const float4*)part)[idx];
    float4 p1 = ((const float4*)(part + MM * 160))[idx];
    float4 p2 = ((const float4*)(part + 2 * MM * 160))[idx];
    float4 p3 = ((const float4*)(part + 3 * MM * 160))[idx];
    float s0 = fast_tanh(p0.x + p1.x + p2.x + p3.x);
    float s1 = fast_tanh(p0.y + p1.y + p2.y + p3.y);
    float s2 = fast_tanh(p0.z + p1.z + p2.z + p3.z);
    float s3 = fast_tanh(p0.w + p1.w + p2.w + p3.w);
    ((__half2*)g1)[idx * 2]     = __floats2half2_rn(s0, s1);
    ((__half2*)g1)[idx * 2 + 1] = __floats2half2_rn(s2, s3);
}

// ----------------------------- GEMM args ------------------------------------
struct GArgs {
    const __half* A[5];
    const __half* B[5];
    void*         C[5];
    const float*  tm[5];
    int ep[5];
    int ch[5];
    int N[5];
    int ldc[5];
    int lda[5];
    int ldb[5];
    int K;
    const float*  x;
    const __half* xxh;
    const float*  bias;
};

__device__ __forceinline__ float4 ep_apply(float4 v, int ep, int grow, int gcol,
                                           int zoff, const float* tmv,
                                           const GArgs& ga)
{
    if (ep == EP_TANH) {
        v.x = fast_tanh(v.x); v.y = fast_tanh(v.y);
        v.z = fast_tanh(v.z); v.w = fast_tanh(v.w);
    } else if (ep == EP_SILU) {
        v.x = fast_silu(v.x); v.y = fast_silu(v.y);
        v.z = fast_silu(v.z); v.w = fast_silu(v.w);
    } else if (ep == EP_EXPW) {
        v.x = __expf(-__expf(ga.bias[gcol]     + v.x));
        v.y = __expf(-__expf(ga.bias[gcol + 1] + v.y));
        v.z = __expf(-__expf(ga.bias[gcol + 2] + v.z));
        v.w = __expf(-__expf(ga.bias[gcol + 3] + v.w));
    } else if (ep == EP_MIX) {
        int ccol = gcol - zoff;
        size_t ix = (size_t)grow * CC + ccol;
        float4 x4 = *(const float4*)(ga.x + ix);
        __half2 hx0 = *(const __half2*)(ga.xxh + ix);
        __half2 hx1 = *(const __half2*)(ga.xxh + ix + 2);
        float2 xxa = __half22float2(hx0);
        float2 xxb = __half22float2(hx1);
        float4 t4 = *(const float4*)(tmv + ccol);
        v.x = fmaf(xxa.x, t4.x + v.x, x4.x);
        v.y = fmaf(xxa.y, t4.y + v.y, x4.y);
        v.z = fmaf(xxb.x, t4.z + v.z, x4.z);
        v.w = fmaf(xxb.y, t4.w + v.w, x4.w);
    }
    return v;
}

// -------------------------- FP16 MMA GEMM, TBM=128 --------------------------
#define TBM 128
#define TBN 128
#define TBK 32
#define OP_B   10240u
#define STG_B  20480u
#define GEMM_DSMEM 81920

#define ISSUE_TILE(tile)                                                       \
    {                                                                          \
        int k0_ = (tile) * TBK;                                                \
        uint32_t sa_ = smb + ((tile) & 3) * STG_B;                             \
        uint32_t sb_ = sa_ + OP_B;                                             \
        int row_ = tid >> 1;                                                   \
        int te_  = (tid & 1) * 16;                                             \
        const __half* Ap_ = A + (size_t)(bm + row_) * lda + k0_ + te_;         \
        cpasync16(sa_ + row_ * 80 + te_ * 2,      Ap_);                        \
        cpasync16(sa_ + row_ * 80 + te_ * 2 + 16, Ap_ + 8);                    \
        const __half* Bp_ = B + (size_t)(bn + row_) * ldb + k0_ + te_;         \
        cpasync16(sb_ + row_ * 80 + te_ * 2,      Bp_);                        \
        cpasync16(sb_ + row_ * 80 + te_ * 2 + 16, Bp_ + 8);                    \
        asm volatile("cp.async.commit_group;");                                \
    }

__global__ void __launch_bounds__(256, 2) gemm_kernel(GArgs ga)
{
    extern __shared__ float sdyn[];

    const int z = blockIdx.z;
    const __half* __restrict__ A = ga.A[z];
    const __half* __restrict__ B = ga.B[z];
    const int N   = ga.N[z];
    const int ldc = ga.ldc[z];
    const int lda = ga.lda[z];
    const int ldb = ga.ldb[z];
    const int K   = ga.K;
    const int ep  = ga.ep[z];
    const int chf = ga.ch[z];

    const int bn = blockIdx.x * TBN;
    if (bn >= N) return;
    const int bm = blockIdx.y * TBM;
    const int zoff = (bn / 768) * 768;

    const int tid  = threadIdx.x;
    const int lane = tid & 31;
    const int wid  = tid >> 5;
    const int gr = lane >> 2, gc = lane & 3;
    const int wm = (wid & 3) * 32;
    const int wn = (wid >> 2) * 64;

    const uint32_t smb = (uint32_t)__cvta_generic_to_shared(sdyn);

    const int p  = lane >> 3;
    const int pr = lane & 7;
    const uint32_t a_lane = smb + (uint32_t)((wm + (p & 1) * 8 + pr) * 80 + (p >> 1) * 16);
    const uint32_t b_lane = smb + OP_B + (uint32_t)((wn + (p >> 1) * 8 + pr) * 80 + (p & 1) * 16);

    float acc[2][8][4];
#pragma unroll
    for (int mi = 0; mi < 2; mi++)
#pragma unroll
        for (int ni = 0; ni < 8; ni++)
#pragma unroll
            for (int c = 0; c < 4; c++) acc[mi][ni][c] = 0.f;

    const int niter = K / TBK;
    ISSUE_TILE(0)
    if (niter > 1) ISSUE_TILE(1)
    if (niter > 2) ISSUE_TILE(2)

    for (int it = 0; it < niter; it++) {
        const int remafter = niter - it - 1;
        if (remafter >= 2)      asm volatile("cp.async.wait_group 2;");
        else if (remafter == 1) asm volatile("cp.async.wait_group 1;");
        else                    asm volatile("cp.async.wait_group 0;");
        __syncthreads();

        if (it + 3 < niter) ISSUE_TILE(it + 3)

        const uint32_t abase = a_lane + (uint32_t)(it & 3) * STG_B;
        const uint32_t bbase = b_lane + (uint32_t)(it & 3) * STG_B;
#pragma unroll
        for (int kk = 0; kk < 2; kk++) {
            uint32_t af[2][4], bf[4][4];
#pragma unroll
            for (int mi = 0; mi < 2; mi++)
                LDSM4(af[mi][0], af[mi][1], af[mi][2], af[mi][3],
                      abase + mi * 1280 + kk * 32)
#pragma unroll
            for (int P = 0; P < 4; P++)
                LDSM4(bf[P][0], bf[P][1], bf[P][2], bf[P][3],
                      bbase + P * 1280 + kk * 32)
#pragma unroll
            for (int mi = 0; mi < 2; mi++)
#pragma unroll
                for (int ni = 0; ni < 8; ni++)
                    mma_f16(acc[mi][ni], af[mi],
                            bf[ni >> 1][(ni & 1) * 2],
                            bf[ni >> 1][(ni & 1) * 2 + 1]);
        }
        __syncthreads();
    }

    float* Cs = sdyn;
#pragma unroll
    for (int mi = 0; mi < 2; mi++)
#pragma unroll
        for (int ni = 0; ni < 8; ni++)
#pragma unroll
            for (int cp = 0; cp < 2; cp++) {
                int row = wm + mi * 16 + gr + cp * 8;
                int col = wn + ni * 8 + 2 * gc;
                *(float2*)&Cs[row * 132 + col] =
                    make_float2(acc[mi][ni][cp * 2], acc[mi][ni][cp * 2 + 1]);
            }
    __syncthreads();

    const float* tmv = ga.tm[bn / 768];
#pragma unroll
    for (int ps = 0; ps < 16; ps++) {
        int row  = ps * 8 + wid;
        int col  = lane * 4;
        int grow = bm + row;
        int gcol = bn + col;
        if (gcol + 3 < N) {
            float4 v = *(float4*)&Cs[row * 132 + col];
            v = ep_apply(v, ep, grow, gcol, zoff, tmv, ga);
            if (chf) {
                __half* Ch = (__half*)ga.C[z];
                *(__half2*)&Ch[(size_t)grow * ldc + gcol]     = __floats2half2_rn(v.x, v.y);
                *(__half2*)&Ch[(size_t)grow * ldc + gcol + 2] = __floats2half2_rn(v.z, v.w);
            } else {
                float* Cf = (float*)ga.C[z];
                *(float4*)&Cf[(size_t)grow * ldc + gcol] = v;
            }
        } else if (gcol < N) {
            for (int e = 0; e < 4 && gcol + e < N; e++) {
                float v0 = Cs[row * 132 + col + e];
                if (ep == EP_TANH) v0 = fast_tanh(v0);
                else if (ep == EP_SILU) v0 = fast_silu(v0);
                else if (ep == EP_EXPW) v0 = __expf(-__expf(ga.bias[gcol + e] + v0));
                else if (ep == EP_MIX) {
                    size_t ix = (size_t)grow * CC + (gcol - zoff) + e;
                    v0 = fmaf(__half2float(ga.xxh[ix]),
                              tmv[(gcol - zoff) + e] + v0, ga.x[ix]);
                }
                if (chf) ((__half*)ga.C[z])[(size_t)grow * ldc + gcol + e] = __float2half_rn(v0);
                else     ((float*)ga.C[z])[(size_t)grow * ldc + gcol + e] = v0;
            }
        }
    }
}

// ------------------------- q_shift + maa_x mix -------------------------------
__global__ void shift_kernel(const float* __restrict__ x,
                             const float* __restrict__ tmx,
                             __half* __restrict__ xxh,
                             __half* __restrict__ xxx)
{
    int idx = blockIdx.x * blockDim.x + threadIdx.x;
    if (idx >= MM * (CC/4)) return;
    int c4i = idx % (CC/4);
    int m   = idx / (CC/4);
    int c   = c4i * 4;
    int b = m >> 10;
    int t = m & 1023;
    int hh = t >> 5;
    int w  = t & 31;
    int q  = c / C4;
    int sh = hh + ((q == 2) ? -1 : (q == 3) ? 1 : 0);
    int sw = w  + ((q == 0) ? -1 : (q == 1) ? 1 : 0);
    float4 xs = make_float4(0.f, 0.f, 0.f, 0.f);
    if (sh >= 0 && sh < HP_ && sw >= 0 && sw < WP_)
        xs = *(const float4*)(x + ((size_t)((b << 10) + (sh << 5) + sw)) * CC + c);
    float4 xv = ((const float4*)x)[idx];
    float4 tm = *(const float4*)(tmx + c);
    float4 d;
    d.x = xs.x - xv.x; d.y = xs.y - xv.y; d.z = xs.z - xv.z; d.w = xs.w - xv.w;
    float o0 = fmaf(d.x, tm.x, xv.x), o1 = fmaf(d.y, tm.y, xv.y);
    float o2 = fmaf(d.z, tm.z, xv.z), o3 = fmaf(d.w, tm.w, xv.w);
    ((__half2*)xxh)[idx * 2]     = __floats2half2_rn(d.x, d.y);
    ((__half2*)xxh)[idx * 2 + 1] = __floats2half2_rn(d.z, d.w);
    ((__half2*)xxx)[idx * 2]     = __floats2half2_rn(o0, o1);
    ((__half2*)xxx)[idx * 2 + 1] = __floats2half2_rn(o2, o3);
}

// ------------------- WKV phase A: intra-chunk + U/d/R~ -----------------------
__global__ void __launch_bounds__(256) wkv_intra_kernel(
    const float* __restrict__ r, const float* __restrict__ k,
    const float* __restrict__ v, const float* __restrict__ dd,
    const float* __restrict__ u, float* __restrict__ y,
    float* __restrict__ gRt, float* __restrict__ gU, float* __restrict__ gD)
{
    __shared__ float sr[CL][36], sk[CL][36], sv[CL][36], se[CL][36];
    __shared__ float scum[CL][36], sexc[CL][36], sKtT[HSZ][36], satt[CL][36];
    __shared__ float sdiag[CL], scend[HSZ], su[HSZ];

    const int hc = blockIdx.x;
    const int head = hc >> 5;
    const int cch  = hc & 31;
    const int b = head / NHD, h = head % NHD;
    const int c0 = cch * CL;
    const int tid  = threadIdx.x;
    const int lane = tid & 31;
    const int wid  = tid >> 5;
    const int tld = tid >> 3;
    const int jld = (tid & 7) << 2;

    if (tid < HSZ) su[tid] = u[h * HSZ + tid];

    const size_t base = (size_t)b * TT * CC + (size_t)h * HSZ;
    size_t g0 = base + (size_t)(c0 + tld) * CC + jld;
    *(float4*)&sr[tld][jld] = *(const float4*)(r  + g0);
    *(float4*)&sk[tld][jld] = *(const float4*)(k  + g0);
    *(float4*)&sv[tld][jld] = *(const float4*)(v  + g0);
    *(float4*)&se[tld][jld] = *(const float4*)(dd + g0);
    __syncthreads();

#pragma unroll
    for (int q = 0; q < 4; q++) {
        int j = wid * 4 + q;
        float vv = se[lane][j];
#pragma unroll
        for (int off = 1; off < 32; off <<= 1) {
            float nb = __shfl_up_sync(0xffffffffu, vv, off);
            if (lane >= off) vv *= nb;
        }
        float ex = __shfl_up_sync(0xffffffffu, vv, 1);
        if (lane == 0) ex = 1.f;
        scum[lane][j] = vv;
        sexc[lane][j] = ex;
        if (lane == 31) scend[j] = vv;
    }
    {
        float pp = 0.f;
#pragma unroll
        for (int e = 0; e < 4; e++)
            pp += sr[tld][jld + e] * su[jld + e] * sk[tld][jld + e];
        pp += __shfl_xor_sync(0xffffffffu, pp, 1);
        pp += __shfl_xor_sync(0xffffffffu, pp, 2);
        pp += __shfl_xor_sync(0xffffffffu, pp, 4);
        if ((lane & 7) == 0) sdiag[tld] = pp;
    }
    __syncthreads();

#pragma unroll
    for (int e = 0; e < 4; e++) {
        int j = jld + e;
        float Ein = scum[tld][j];
        float Eex = sexc[tld][j];
        float rw  = sr[tld][j];
        float kw  = sk[tld][j];
        float kt  = __fdividef(kw, Ein);
        sr[tld][j]   = rw * Eex;
        sKtT[j][tld] = kt;
        scum[tld][j] = kt * scend[j];
    }
    __syncthreads();

    {
        const int t = tld, t4 = jld;
        float a0 = 0.f, a1 = 0.f, a2 = 0.f, a3 = 0.f;
#pragma unroll
        for (int j = 0; j < HSZ; j++) {
            float rt = sr[t][j];
            float4 kt = *(const float4*)&sKtT[j][t4];
            a0 = fmaf(rt, kt.x, a0); a1 = fmaf(rt, kt.y, a1);
            a2 = fmaf(rt, kt.z, a2); a3 = fmaf(rt, kt.w, a3);
        }
        float dv = sdiag[t];
        satt[t][t4+0] = (t4+0 < t) ? a0 : ((t4+0 == t) ? dv : 0.f);
        satt[t][t4+1] = (t4+1 < t) ? a1 : ((t4+1 == t) ? dv : 0.f);
        satt[t][t4+2] = (t4+2 < t) ? a2 : ((t4+2 == t) ? dv : 0.f);
        satt[t][t4+3] = (t4+3 < t) ? a3 : ((t4+3 == t) ? dv : 0.f);
    }
    __syncthreads();

    *(float4*)(gRt + (size_t)hc * 1024 + tld * 32 + jld) = *(float4*)&sr[tld][jld];
    if (tid < HSZ) gD[(size_t)hc * 32 + tid] = scend[tid];

    {
        const int t = tld, i4 = jld;
        float4 acc = make_float4(0.f, 0.f, 0.f, 0.f);
#pragma unroll
        for (int tau = 0; tau < CL; tau++) {
            float at = satt[t][tau];
            float4 vv = *(const float4*)&sv[tau][i4];
            acc.x = fmaf(at, vv.x, acc.x); acc.y = fmaf(at, vv.y, acc.y);
            acc.z = fmaf(at, vv.z, acc.z); acc.w = fmaf(at, vv.w, acc.w);
        }
        *(float4*)(y + base + (size_t)(c0 + t) * CC + i4) = acc;
    }

    {
        const int j = tld, i4 = jld;
        float4 s = make_float4(0.f, 0.f, 0.f, 0.f);
#pragma unroll
        for (int tau = 0; tau < CL; tau++) {
            float kh = scum[tau][j];
            float4 vv = *(const float4*)&sv[tau][i4];
            s.x = fmaf(kh, vv.x, s.x); s.y = fmaf(kh, vv.y, s.y);
            s.z = fmaf(kh, vv.z, s.z); s.w = fmaf(kh, vv.w, s.w);
        }
        *(float4*)(gU + (size_t)hc * 1024 + j * 32 + i4) = s;
    }
}

// ------------------- WKV phase B: inter-chunk prefix scan --------------------
__global__ void __launch_bounds__(1024) wkv_scan_kernel(
    const float* __restrict__ gU, const float* __restrict__ gD,
    float* __restrict__ gS)
{
    const int head = blockIdx.x;
    const int j = threadIdx.x >> 5;
    const int i = threadIdx.x & 31;
    float s = 0.f;
#pragma unroll
    for (int c = 0; c < NCH; c++) {
        size_t e = ((size_t)(head * NCH + c) * 32 + j) * 32 + i;
        gS[e] = s;
        float d = gD[(size_t)(head * NCH + c) * 32 + j];
        s = fmaf(d, s, gU[e]);
    }
}

// ------------------- WKV phase C: y += R~ @ S_in ----------------------------
__global__ void __launch_bounds__(256) wkv_inter_kernel(
    const float* __restrict__ gRt, const float* __restrict__ gS,
    float* __restrict__ y)
{
    __shared__ float srt[CL][36], ss[HSZ][36];

    const int hc = blockIdx.x;
    const int head = hc >> 5;
    const int cch  = hc & 31;
    const int b = head / NHD, h = head % NHD;
    const int c0 = cch * CL;
    const int tid = threadIdx.x;
    const int tld = tid >> 3;
    const int jld = (tid & 7) << 2;

    *(float4*)&srt[tld][jld] = *(const float4*)(gRt + (size_t)hc * 1024 + tld * 32 + jld);
    *(float4*)&ss[tld][jld]  = *(const float4*)(gS  + (size_t)hc * 1024 + tld * 32 + jld);
    __syncthreads();

    const size_t base = (size_t)b * TT * CC + (size_t)h * HSZ;
    const int t = tld, i4 = jld;
    float4 acc = *(float4*)(y + base + (size_t)(c0 + t) * CC + i4);
#pragma unroll
    for (int j = 0; j < HSZ; j++) {
        float rt = srt[t][j];
        float4 sj = *(const float4*)&ss[j][i4];
        acc.x = fmaf(rt, sj.x, acc.x); acc.y = fmaf(rt, sj.y, acc.y);
        acc.z = fmaf(rt, sj.z, acc.z); acc.w = fmaf(rt, sj.w, acc.w);
    }
    *(float4*)(y + base + (size_t)(c0 + t) * CC + i4) = acc;
}

// --------------------------- LayerNorm * gate (half out) --------------------
__global__ void __launch_bounds__(256) ln_gate_kernel(
    const float* __restrict__ y, const float* __restrict__ g,
    const float* __restrict__ lw, const float* __restrict__ lb,
    __half* __restrict__ out)
{
    __shared__ float red[8];
    int m = blockIdx.x;
    int t = threadIdx.x;
    size_t base = (size_t)m * CC;
    float v0 = y[base + t], v1 = y[base + t + 256], v2 = y[base + t + 512];
    float s = v0 + v1 + v2;
#pragma unroll
    for (int o = 16; o; o >>= 1) s += __shfl_xor_sync(0xffffffffu, s, o);
    if ((t & 31) == 0) red[t >> 5] = s;
    __syncthreads();
    float tot = red[0]+red[1]+red[2]+red[3]+red[4]+red[5]+red[6]+red[7];
    float mu = tot * (1.f / CC);
    float d0 = v0 - mu, d1 = v1 - mu, d2 = v2 - mu;
    float q = d0*d0 + d1*d1 + d2*d2;
#pragma unroll
    for (int o = 16; o; o >>= 1) q += __shfl_xor_sync(0xffffffffu, q, o);
    __syncthreads();
    if ((t & 31) == 0) red[t >> 5] = q;
    __syncthreads();
    float var = (red[0]+red[1]+red[2]+red[3]+red[4]+red[5]+red[6]+red[7]) * (1.f / CC);
    float inv = rsqrtf(var + 1e-5f);
    out[base + t]       = __float2half_rn((d0 * inv * lw[t]       + lb[t])       * g[base + t]);
    out[base + t + 256] = __float2half_rn((d1 * inv * lw[t + 256] + lb[t + 256]) * g[base + t + 256]);
    out[base + t + 512] = __float2half_rn((d2 * inv * lw[t + 512] + lb[t + 512]) * g[base + t + 512]);
}

// ------------------------------- launcher -----------------------------------
extern "C" void kernel_launch(void* const* d_in, const int* in_sizes, int n_in,
                              void* d_out, int out_size)
{
    const float* x    = (const float*)d_in[0];
    const float* tmx  = (const float*)d_in[1];
    const float* tmw  = (const float*)d_in[2];
    const float* tmk  = (const float*)d_in[3];
    const float* tmv  = (const float*)d_in[4];
    const float* tmr  = (const float*)d_in[5];
    const float* tmg  = (const float*)d_in[6];
    const float* w1   = (const float*)d_in[7];
    const float* w2   = (const float*)d_in[8];
    const float* tdec = (const float*)d_in[9];
    const float* dw1  = (const float*)d_in[10];
    const float* dw2  = (const float*)d_in[11];
    const float* faaa = (const float*)d_in[12];
    const float* W_r  = (const float*)d_in[13];
    const float* W_k  = (const float*)d_in[14];
    const float* W_v  = (const float*)d_in[15];
    const float* W_g  = (const float*)d_in[16];
    const float* W_o  = (const float*)d_in[17];
    const float* lnw  = (const float*)d_in[18];
    const float* lnb  = (const float*)d_in[19];
    float* out = (float*)d_out;

    static cudaStream_t s2 = nullptr;
    static cudaEvent_t evFork1, evJoin1, evFork2, evJoin2;
    if (!s2) {
        cudaFuncSetAttribute(gemm_kernel,
                             cudaFuncAttributeMaxDynamicSharedMemorySize,
                             GEMM_DSMEM);
        cudaStreamCreateWithFlags(&s2, cudaStreamNonBlocking);
        cudaEventCreateWithFlags(&evFork1, cudaEventDisableTiming);
        cudaEventCreateWithFlags(&evJoin1, cudaEventDisableTiming);
        cudaEventCreateWithFlags(&evFork2, cudaEventDisableTiming);
        cudaEventCreateWithFlags(&evJoin2, cudaEventDisableTiming);
    }

    float* buf = nullptr;
    cudaGetSymbolAddress((void**)&buf, g_scratch);

    // fp32 buffers
    float* gRt = buf + 5 * SSLOT;
    float* gU  = buf + 6 * SSLOT;
    float* rr  = buf + 7 * SSLOT;     // also reused for G1 split-K partials
    float* kk  = buf + 8 * SSLOT;
    float* vv  = buf + 9 * SSLOT;
    float* gg  = buf + 10 * SSLOT;
    float* ddv = buf + 11 * SSLOT;
    float* yy  = buf + 12 * SSLOT;
    float* gS  = buf + 15 * SSLOT;
    float* g1p = rr;

    // fp16 buffers
    __half* xxh  = (__half*)buf;
    __half* xxx  = (__half*)(buf + 1 * SSLOT);
    __half* mAll = (__half*)(buf + 2 * SSLOT);
    __half* G1   = (__half*)(buf + 13 * SSLOT);
    __half* ww   = (__half*)(buf + 13 * SSLOT + 393216);
    float*  gD   = buf + 13 * SSLOT + 524288;
    __half* bmix = (__half*)(buf + 13 * SSLOT + 786432);
    __half* dw1t = (__half*)(buf + 13 * SSLOT + 1100000);
    __half* dw2t = dw1t + 98304;
    __half* ln   = (__half*)buf;

    __half* Wt_r = (__half*)(buf + 14 * SSLOT);
    __half* Wt_k = Wt_r + 589824;
    __half* Wt_v = Wt_k + 589824;
    __half* Wt_g = Wt_v + 589824;
    __half* Wt_o = Wt_g + 589824;
    __half* w1t  = Wt_o + 589824;

    const int EW4 = (MM * (CC/4) + 255) / 256;

    // ---- fork 1: weights prep (s2) || shift (s0) ----
    cudaEventRecord(evFork1, 0);
    cudaStreamWaitEvent(s2, evFork1, 0);

    {
        TArgs ta = {};
        const float* srcs[NTR] = {W_r, W_k, W_v, W_g, W_o, w1, dw1, dw2};
        __half* dsts[NTR] = {Wt_r, Wt_k, Wt_v, Wt_g, Wt_o, w1t, dw1t, dw2t};
        int Ks[NTR]  = {768,768,768,768,768, 768, 768, 64};
        int Ns[NTR]  = {768,768,768,768,768, 160,  64, 768};
        int Nps[NTR] = {768,768,768,768,768, 256, 128, 768};
        for (int i = 0; i < NTR; i++) {
            ta.src[i] = srcs[i]; ta.dst[i] = dsts[i];
            ta.K[i] = Ks[i]; ta.N[i] = Ns[i]; ta.Np[i] = Nps[i];
        }
        transpose_kernel<<<dim3(24, 24, NTR), dim3(32, 8), 0, s2>>>(ta);
        build_bmix_kernel<<<(3840*160 + 255)/256, 256, 0, s2>>>(w2, bmix);
        cudaEventRecord(evJoin1, s2);
    }

    shift_kernel<<<EW4, 256>>>(x, tmx, xxh, xxx);

    cudaStreamWaitEvent(0, evJoin1, 0);

    // G1 split-K x4: partials, then reduce+tanh -> half G1
    {
        GArgs a = {};
        for (int s = 0; s < 4; s++) {
            a.A[s] = xxx + s * 192;
            a.B[s] = w1t + s * 192;
            a.C[s] = g1p + (size_t)s * MM * 160;
            a.ep[s] = EP_NONE; a.ch[s] = 0; a.N[s] = 160; a.ldc[s] = 160;
            a.lda[s] = CC; a.ldb[s] = CC;
        }
        a.K = 192;
        gemm_kernel<<<dim3(2, 32, 4), 256, GEMM_DSMEM>>>(a);
        g1_reduce_kernel<<<(MM * 160 / 4 + 255) / 256, 256>>>(g1p, G1);
    }

    // fused mix GEMM
    {
        GArgs a = {};
        a.A[0] = G1; a.B[0] = bmix; a.C[0] = mAll;
        a.ep[0] = EP_MIX; a.ch[0] = 1; a.N[0] = 3840; a.ldc[0] = 3840;
        a.lda[0] = 160; a.ldb[0] = 160; a.K = 160;
        a.tm[0] = tmw; a.tm[1] = tmk; a.tm[2] = tmv; a.tm[3] = tmr; a.tm[4] = tmg;
        a.x = x; a.xxh = xxh;
        gemm_kernel<<<dim3(30, 32, 1), 256, GEMM_DSMEM>>>(a);
    }

    // ---- fork 2: decay chain (s2) || r,k,v,g projections (s0) ----
    cudaEventRecord(evFork2, 0);
    cudaStreamWaitEvent(s2, evFork2, 0);

    {
        GArgs a = {};
        a.A[0] = mAll + 0*768; a.B[0] = dw1t; a.C[0] = ww;
        a.ep[0] = EP_TANH; a.ch[0] = 1; a.N[0] = 64; a.ldc[0] = 64;
        a.lda[0] = 3840; a.ldb[0] = CC; a.K = CC;
        gemm_kernel<<<dim3(1, 32, 1), 256, GEMM_DSMEM, s2>>>(a);

        GArgs b = {};
        b.A[0] = ww; b.B[0] = dw2t; b.C[0] = ddv;
        b.ep[0] = EP_EXPW; b.ch[0] = 0; b.N[0] = CC; b.ldc[0] = CC;
        b.lda[0] = 64; b.ldb[0] = 64; b.K = 64;
        b.bias = tdec;
        gemm_kernel<<<dim3(6, 32, 1), 256, GEMM_DSMEM, s2>>>(b);
        cudaEventRecord(evJoin2, s2);
    }

    {
        GArgs a = {};
        a.A[0] = mAll + 3*768; a.B[0] = Wt_r; a.C[0] = rr; a.ep[0] = EP_NONE; a.ch[0] = 0; a.N[0] = CC; a.ldc[0] = CC; a.lda[0] = 3840; a.ldb[0] = CC;
        a.A[1] = mAll + 1*768; a.B[1] = Wt_k; a.C[1] = kk; a.ep[1] = EP_NONE; a.ch[1] = 0; a.N[1] = CC; a.ldc[1] = CC; a.lda[1] = 3840; a.ldb[1] = CC;
        a.A[2] = mAll + 2*768; a.B[2] = Wt_v; a.C[2] = vv; a.ep[2] = EP_NONE; a.ch[2] = 0; a.N[2] = CC; a.ldc[2] = CC; a.lda[2] = 3840; a.ldb[2] = CC;
        a.A[3] = mAll + 4*768; a.B[3] = Wt_g; a.C[3] = gg; a.ep[3] = EP_SILU; a.ch[3] = 0; a.N[3] = CC; a.ldc[3] = CC; a.lda[3] = 3840; a.ldb[3] = CC;
        a.K = CC;
        gemm_kernel<<<dim3(6, 32, 4), 256, GEMM_DSMEM>>>(a);
    }

    cudaStreamWaitEvent(0, evJoin2, 0);

    // WKV: intra -> scan -> inter
    wkv_intra_kernel<<<BBATCH * NHD * NCH, 256>>>(rr, kk, vv, ddv, faaa, yy,
                                                  gRt, gU, gD);
    wkv_scan_kernel<<<BBATCH * NHD, 1024>>>(gU, gD, gS);
    wkv_inter_kernel<<<BBATCH * NHD * NCH, 256>>>(gRt, gS, yy);

    // LayerNorm * gate -> half ln
    ln_gate_kernel<<<MM, 256>>>(yy, gg, lnw, lnb, ln);

    // output projection
    {
        GArgs a = {};
        a.A[0] = ln; a.B[0] = Wt_o; a.C[0] = out;
        a.ep[0] = EP_NONE; a.ch[0] = 0; a.N[0] = CC; a.ldc[0] = CC;
        a.lda[0] = CC; a.ldb[0] = CC; a.K = CC;
        gemm_kernel<<<dim3(6, 32, 1), 256, GEMM_DSMEM>>>(a);
    }

    (void)in_sizes; (void)n_in; (void)out_size;
}